// round 7
// baseline (speedup 1.0000x reference)
#include <cuda_runtime.h>
#include <math.h>

// EdgeAttr: out[e][c] = sigmoid( sum_k exp(-(((d_e - 0.4k)/0.375)^2)) * W[k][c] + b[c] )
// Inputs: pos [N,3] f32, edge_index [2,E] int32, W [16,128] f32, b [128] f32
// Output: [E,128] f32
//
// R7: R5-proven skeleton + pre-duplicated (r,r) RBF operands in smem so the matvec
//     consumes packed f32x2 multiplicands straight from LDS.128 (no pack MOVs).
//     Sigmoid via proven ex2/rcp. W in regs; persistent blocks; double buffer;
//     2-deep gather pipeline; streaming stores.

#define THREADS 256
#define E_TILE  64
#define HID     128
#define DC      16

__device__ __forceinline__ unsigned long long pack2(float lo, float hi) {
    unsigned long long r;
    asm("mov.b64 %0, {%1, %2};" : "=l"(r) : "f"(lo), "f"(hi));
    return r;
}
__device__ __forceinline__ void unpack2(unsigned long long v, float& lo, float& hi) {
    asm("mov.b64 {%0, %1}, %2;" : "=f"(lo), "=f"(hi) : "l"(v));
}
__device__ __forceinline__ unsigned long long fma2(unsigned long long a,
                                                   unsigned long long b,
                                                   unsigned long long c) {
    unsigned long long d;
    asm("fma.rn.f32x2 %0, %1, %2, %3;" : "=l"(d) : "l"(a), "l"(b), "l"(c));
    return d;
}
__device__ __forceinline__ float fast_sigmoid(float x) {
    // 1 / (1 + 2^(-x*log2e)) : 2 MUFU + 1 FMUL + 1 FADD  (proven in R4/R5)
    float e, r;
    asm("ex2.approx.f32 %0, %1;" : "=f"(e) : "f"(-1.4426950408889634f * x));
    asm("rcp.approx.f32 %0, %1;" : "=f"(r) : "f"(1.0f + e));
    return r;
}

__global__ __launch_bounds__(THREADS, 2)
void edge_attr_kernel(const float* __restrict__ pos,
                      const int* __restrict__ edge_index,
                      const float* __restrict__ W,
                      const float* __restrict__ bias,
                      float* __restrict__ out,
                      int n_edges, int n_tiles)
{
    // RBF tile, each value duplicated into a packed f32x2: sR[buf][edge][k] = (r_k, r_k).
    __shared__ __align__(16) unsigned long long sR[2][E_TILE][DC];   // 16 KB

    const int t    = threadIdx.x;
    const int lane = t & 31;
    const int w    = t >> 5;
    const int c    = lane * 4;            // this lane's 4 output columns

    // ---- W slice + bias into registers (once per block) ----
    unsigned long long wreg[2 * DC];      // wreg[2k]=(W[k][c],W[k][c+1]), wreg[2k+1]=(c+2,c+3)
    #pragma unroll
    for (int kk = 0; kk < DC; kk++) {
        const float4 wv = *reinterpret_cast<const float4*>(W + kk * HID + c);
        wreg[2 * kk]     = pack2(wv.x, wv.y);
        wreg[2 * kk + 1] = pack2(wv.z, wv.w);
    }
    unsigned long long b01, b23;
    {
        const float4 bv = *reinterpret_cast<const float4*>(bias + c);
        b01 = pack2(bv.x, bv.y);
        b23 = pack2(bv.z, bv.w);
    }

    // Phase-1 role: 4 threads per edge, each computes 4 RBF terms
    const int el = t >> 2;                // local edge 0..63
    const int q  = t & 3;                 // quarter 0..3
    const long long stride = gridDim.x;

    // ---- gather pipeline registers ----
    int   ia2, ib2;
    float pax, pay, paz, pbx, pby, pbz;

    long long tile = blockIdx.x;
    {   // prologue: pos for tile, idx for tile+stride
        int ge = (int)min(tile * E_TILE + el, (long long)n_edges - 1);
        const int ia = edge_index[ge];
        const int ib = edge_index[n_edges + ge];
        pax = pos[3 * ia]; pay = pos[3 * ia + 1]; paz = pos[3 * ia + 2];
        pbx = pos[3 * ib]; pby = pos[3 * ib + 1]; pbz = pos[3 * ib + 2];
        int ge2 = (int)min((tile + stride) * E_TILE + el, (long long)n_edges - 1);
        ia2 = edge_index[ge2];
        ib2 = edge_index[n_edges + ge2];
    }

    int buf = 0;
    for (; tile < n_tiles; tile += stride) {
        // ---- phase 1: RBF for current tile, stored duplicated (r,r) ----
        {
            const float dx = pax - pbx, dy = pay - pby, dz = paz - pbz;
            const float d  = sqrtf(fmaf(dx, dx, fmaf(dy, dy, dz * dz)));
            float r[4];
            #pragma unroll
            for (int j4 = 0; j4 < 4; j4++) {
                const float u = (d - 0.4f * (float)(q * 4 + j4)) * 2.6666666667f;
                r[j4] = __expf(-u * u);
            }
            ulonglong2 s0, s1;
            s0.x = pack2(r[0], r[0]);  s0.y = pack2(r[1], r[1]);
            s1.x = pack2(r[2], r[2]);  s1.y = pack2(r[3], r[3]);
            *reinterpret_cast<ulonglong2*>(&sR[buf][el][q * 4])     = s0;  // 16B store
            *reinterpret_cast<ulonglong2*>(&sR[buf][el][q * 4 + 2]) = s1;  // 16B store
        }
        // ---- prefetch: pos for tile+stride, idx for tile+2*stride ----
        {
            pax = pos[3 * ia2]; pay = pos[3 * ia2 + 1]; paz = pos[3 * ia2 + 2];
            pbx = pos[3 * ib2]; pby = pos[3 * ib2 + 1]; pbz = pos[3 * ib2 + 2];
            int ge2 = (int)min((tile + 2 * stride) * E_TILE + el, (long long)n_edges - 1);
            ia2 = edge_index[ge2];
            ib2 = edge_index[n_edges + ge2];
        }
        __syncthreads();

        // ---- phase 2: matvec (W in regs, f32x2, packed smem multiplicands) ----
        const int e0 = (int)(tile * E_TILE);
        #pragma unroll
        for (int k = 0; k < 8; k++) {
            const int elx = (w << 3) + k;
            const int ge  = e0 + elx;

            unsigned long long a0 = b01, a1 = b23;
            #pragma unroll
            for (int kq = 0; kq < 8; kq++) {
                // 16B broadcast LDS = packed (r,r) for k=2kq and 2kq+1
                const ulonglong2 rr = *reinterpret_cast<const ulonglong2*>(&sR[buf][elx][2 * kq]);
                a0 = fma2(rr.x, wreg[4 * kq + 0], a0);
                a1 = fma2(rr.x, wreg[4 * kq + 1], a1);
                a0 = fma2(rr.y, wreg[4 * kq + 2], a0);
                a1 = fma2(rr.y, wreg[4 * kq + 3], a1);
            }

            float x0, x1, x2, x3;
            unpack2(a0, x0, x1);
            unpack2(a1, x2, x3);
            const float4 o = make_float4(fast_sigmoid(x0), fast_sigmoid(x1),
                                         fast_sigmoid(x2), fast_sigmoid(x3));
            if (ge < n_edges)
                __stcs(reinterpret_cast<float4*>(out + (size_t)ge * HID + c), o);
        }
        buf ^= 1;
    }
}

extern "C" void kernel_launch(void* const* d_in, const int* in_sizes, int n_in,
                              void* d_out, int out_size)
{
    const float* pos = (const float*)d_in[0];
    const int*   ei  = (const int*)d_in[1];
    const float* W   = (const float*)d_in[2];
    const float* b   = (const float*)d_in[3];
    float*       out = (float*)d_out;

    const int n_edges = out_size / HID;
    const int n_tiles = (n_edges + E_TILE - 1) / E_TILE;
    int blocks = 148 * 8;                    // persistent grid
    if (blocks > n_tiles) blocks = n_tiles;

    edge_attr_kernel<<<blocks, THREADS>>>(pos, ei, W, b, out, n_edges, n_tiles);
}